// round 5
// baseline (speedup 1.0000x reference)
#include <cuda_runtime.h>
#include <cuda_bf16.h>
#include <stdint.h>

// ---------------------------------------------------------------------------
// Problem dims (fixed)
// ---------------------------------------------------------------------------
#define M_DIM 8192
#define N_DIM 4096
#define K_DIM 4224
#define KBYTES 2112   // K/2 packed bytes per row (one int32 per byte)
#define KBLKS  264    // K/16 scale blocks per row

// GEMM tiling: fp8 e4m3 path (mma.sync.m16n8k32 is base sm_89+ PTX, not 'a'-gated)
#define BM 128
#define BN 256
#define BK 128                          // fp8 -> 128 bytes per row (SW128 native)
#define KITERS 33                       // 4224 / 128
#define STAGES 4
#define AB (BM * BK)                    // 16384 bytes per A stage
#define BB (BN * BK)                    // 32768 bytes per B stage
#define STB (AB + BB)                   // 49152
#define SMEM_DYN (1024 + STAGES * STB)  // 197632 bytes

// ---------------------------------------------------------------------------
// Device scratch (allocation-free rule: __device__ globals), fp8 e4m3 storage
// ---------------------------------------------------------------------------
__device__ uint8_t g_A[(size_t)M_DIM * K_DIM];
__device__ uint8_t g_B[(size_t)N_DIM * K_DIM];

// ---------------------------------------------------------------------------
// Dequant: packed fp4 (one int per byte, 2 nibbles LSB-first) * 2^(sf-127)
// -> e4m3 row-major. One thread per (row, 16-elem block), 16B store.
// All products are exactly representable in e4m3 except sf=118 & mag in
// {0.5,1.5} (err 2^-10, negligible vs the large-scale blocks dominating y).
// ---------------------------------------------------------------------------
__global__ void dequant_kernel(const int* __restrict__ packed,
                               const int* __restrict__ sf,
                               int total, int which) {
    int idx = blockIdx.x * blockDim.x + threadIdx.x;
    if (idx >= total) return;
    uint8_t* __restrict__ out = which ? g_B : g_A;
    int r = idx / KBLKS;
    int b = idx - r * KBLKS;

    const int4* p = reinterpret_cast<const int4*>(packed + (size_t)r * KBYTES + b * 8);
    int4 p0 = p[0];
    int4 p1 = p[1];
    // 2^(sf-127) * 0.5 (the 0.5 un-doubles the byte LUT)
    float s2 = __uint_as_float(((unsigned)sf[(size_t)r * KBLKS + b]) << 23) * 0.5f;

    int v[8] = {p0.x, p0.y, p0.z, p0.w, p1.x, p1.y, p1.z, p1.w};
    unsigned short o[8];
#pragma unroll
    for (int i = 0; i < 8; i++) {
        int vi = v[i];
        unsigned sel = (unsigned)vi & 0x77u;  // nib0 = lo mag, nib1 = hi mag
        unsigned mags = __byte_perm(0x03020100u, 0x0C080604u, sel);
        float flo = (float)(mags & 0xFFu) * s2;
        float fhi = (float)((mags >> 8) & 0xFFu) * s2;
        unsigned blo = __float_as_uint(flo) ^ (((unsigned)vi & 8u) << 28);
        unsigned bhi = __float_as_uint(fhi) ^ (((unsigned)vi & 128u) << 24);
        unsigned short pk;
        asm("cvt.rn.satfinite.e4m3x2.f32 %0, %1, %2;"
            : "=h"(pk) : "f"(__uint_as_float(bhi)), "f"(__uint_as_float(blo)));
        o[i] = pk;  // low byte = element 2j, high byte = element 2j+1
    }
    uint4* dst = reinterpret_cast<uint4*>(out + (size_t)r * K_DIM + b * 16);
    *dst = *reinterpret_cast<uint4*>(&o[0]);
}

// ---------------------------------------------------------------------------
// Helpers
// ---------------------------------------------------------------------------
__device__ __forceinline__ uint32_t smem_u32(const void* p) {
    uint32_t a;
    asm("{ .reg .u64 t; cvta.to.shared.u64 t, %1; cvt.u32.u64 %0, t; }" : "=r"(a) : "l"(p));
    return a;
}

template <int N>
__device__ __forceinline__ void cp_wait() {
    asm volatile("cp.async.wait_group %0;" :: "n"(N) : "memory");
}
__device__ __forceinline__ void cp_commit() {
    asm volatile("cp.async.commit_group;" ::: "memory");
}

__device__ __forceinline__ void ldsm4(uint32_t* r, uint32_t addr) {
    asm volatile("ldmatrix.sync.aligned.m8n8.x4.shared.b16 {%0,%1,%2,%3}, [%4];"
                 : "=r"(r[0]), "=r"(r[1]), "=r"(r[2]), "=r"(r[3]) : "r"(addr));
}

// fp8 e4m3 MMA, f32 accumulate, m16n8k32
__device__ __forceinline__ void mma_fp8(float* d, const uint32_t* a, const uint32_t* b) {
    asm volatile(
        "mma.sync.aligned.m16n8k32.row.col.f32.e4m3.e4m3.f32 "
        "{%0,%1,%2,%3}, {%4,%5,%6,%7}, {%8,%9}, {%0,%1,%2,%3};"
        : "+f"(d[0]), "+f"(d[1]), "+f"(d[2]), "+f"(d[3])
        : "r"(a[0]), "r"(a[1]), "r"(a[2]), "r"(a[3]), "r"(b[0]), "r"(b[1]));
}

// Swizzle: XOR bits[6:4] with bits[9:7] (128B rows, 16B granules)
__device__ __forceinline__ uint32_t swz(uint32_t off) {
    return off ^ ((off >> 3) & 0x70);
}

// Fill one (stage, kiter): A 128x128 fp8 (16KB) + B 256x128 fp8 (32KB), SW128.
// 256 threads x 12 cp.async(16B) each. 8 x 16B segments per 128B row.
__device__ __forceinline__ void load_stage(uint32_t tiles, int stage, int kit,
                                           int m0, int n0, int tid) {
    uint32_t sbase = tiles + stage * STB;
    int k0 = kit * BK;
#pragma unroll
    for (int i = 0; i < 4; i++) {
        int c = tid + i * 256;            // 0..1023
        int row = c >> 3, seg = c & 7;
        const uint8_t* src = g_A + (size_t)(m0 + row) * K_DIM + k0 + seg * 16;
        uint32_t dst = sbase + swz(row * 128 + seg * 16);
        asm volatile("cp.async.cg.shared.global [%0], [%1], 16;" :: "r"(dst), "l"(src));
    }
#pragma unroll
    for (int i = 0; i < 8; i++) {
        int c = tid + i * 256;            // 0..2047
        int row = c >> 3, seg = c & 7;
        const uint8_t* src = g_B + (size_t)(n0 + row) * K_DIM + k0 + seg * 16;
        uint32_t dst = sbase + AB + swz(row * 128 + seg * 16);
        asm volatile("cp.async.cg.shared.global [%0], [%1], 16;" :: "r"(dst), "l"(src));
    }
}

// ---------------------------------------------------------------------------
// fp8 GEMM via mma.sync m16n8k32: CTA 128x256, 8 warps (2m x 4n),
// warp tile 64x64, 4-stage cp.async pipeline, fused scale+bias epilogue.
// ---------------------------------------------------------------------------
__global__ void __launch_bounds__(256, 1)
gemm_kernel(const float* __restrict__ scale_p,
            const float* __restrict__ bias,
            float* __restrict__ out) {
    extern __shared__ char smem_raw[];
    uint32_t tiles = (smem_u32(smem_raw) + 1023) & ~1023u;

    int tid = threadIdx.x;
    int wid = tid >> 5;
    int lane = tid & 31;
    int m0 = blockIdx.y * BM;
    int n0 = blockIdx.x * BN;
    int wm = wid & 1;    // 2 m-slices of 64 rows
    int wn = wid >> 1;   // 4 n-slices of 64 cols

    float acc[4][8][4];
#pragma unroll
    for (int a = 0; a < 4; a++)
#pragma unroll
        for (int b = 0; b < 8; b++)
#pragma unroll
            for (int c = 0; c < 4; c++) acc[a][b][c] = 0.0f;

    // Prologue: stages 0..2
#pragma unroll
    for (int s = 0; s < STAGES - 1; s++) {
        load_stage(tiles, s, s, m0, n0, tid);
        cp_commit();
    }

    for (int it = 0; it < KITERS; it++) {
        int s = it & (STAGES - 1);
        cp_wait<STAGES - 2>();
        __syncthreads();

        int nit = it + STAGES - 1;
        if (nit < KITERS) load_stage(tiles, nit & (STAGES - 1), nit, m0, n0, tid);
        cp_commit();

        uint32_t abase = tiles + s * STB;
        uint32_t bbase = abase + AB;

#pragma unroll
        for (int ks = 0; ks < 4; ks++) {           // BK=128 -> 4 x k32
            // A fragment: rows wm*64+mf*16+(lane&15), k-bytes ks*32 + (lane>>4)*16
            uint32_t afr[4][4];
#pragma unroll
            for (int mf = 0; mf < 4; mf++) {
                int row = wm * 64 + mf * 16 + (lane & 15);
                uint32_t off = row * 128 + ks * 32 + ((lane >> 4) << 4);
                ldsm4(afr[mf], abase + swz(off));
            }
            // B fragment: n-rows wn*64+np*16+(lane&7)+((lane>>4)<<3),
            // k-bytes ks*32 + ((lane>>3)&1)*16. x4 -> (b0,b1) of two n8 groups.
            uint32_t bfr[8][2];
#pragma unroll
            for (int np = 0; np < 4; np++) {
                int row = wn * 64 + np * 16 + (lane & 7) + ((lane >> 4) << 3);
                uint32_t off = row * 128 + ks * 32 + (((lane >> 3) & 1) << 4);
                uint32_t r[4];
                ldsm4(r, bbase + swz(off));
                bfr[np * 2 + 0][0] = r[0]; bfr[np * 2 + 0][1] = r[1];
                bfr[np * 2 + 1][0] = r[2]; bfr[np * 2 + 1][1] = r[3];
            }
#pragma unroll
            for (int mf = 0; mf < 4; mf++)
#pragma unroll
                for (int ng = 0; ng < 8; ng++)
                    mma_fp8(acc[mf][ng], afr[mf], bfr[ng]);
        }
    }

    // Epilogue: scale * acc + bias, f32 out (row-major [M, N])
    float sc = __ldg(scale_p);
#pragma unroll
    for (int mf = 0; mf < 4; mf++) {
#pragma unroll
        for (int ng = 0; ng < 8; ng++) {
            int m = m0 + wm * 64 + mf * 16 + (lane >> 2);
            int n = n0 + wn * 64 + ng * 8 + (lane & 3) * 2;
            float2 bb = *reinterpret_cast<const float2*>(bias + n);
            float2 v;
            v.x = acc[mf][ng][0] * sc + bb.x;
            v.y = acc[mf][ng][1] * sc + bb.y;
            *reinterpret_cast<float2*>(out + (size_t)m * N_DIM + n) = v;
            v.x = acc[mf][ng][2] * sc + bb.x;
            v.y = acc[mf][ng][3] * sc + bb.y;
            *reinterpret_cast<float2*>(out + (size_t)(m + 8) * N_DIM + n) = v;
        }
    }
}

// ---------------------------------------------------------------------------
// Launch
// ---------------------------------------------------------------------------
extern "C" void kernel_launch(void* const* d_in, const int* in_sizes, int n_in,
                              void* d_out, int out_size) {
    const int*   A_packed = (const int*)d_in[0];
    const int*   SFA      = (const int*)d_in[1];
    const float* scale    = (const float*)d_in[2];
    const int*   B_packed = (const int*)d_in[3];
    const int*   SFB      = (const int*)d_in[4];
    const float* bias     = (const float*)d_in[5];
    float*       out      = (float*)d_out;

    int totA = M_DIM * KBLKS;  // 2,162,688
    int totB = N_DIM * KBLKS;  // 1,081,344
    dequant_kernel<<<(totA + 255) / 256, 256>>>(A_packed, SFA, totA, 0);
    dequant_kernel<<<(totB + 255) / 256, 256>>>(B_packed, SFB, totB, 1);

    static int configured = 0;
    if (!configured) {
        cudaFuncSetAttribute(gemm_kernel, cudaFuncAttributeMaxDynamicSharedMemorySize, SMEM_DYN);
        configured = 1;
    }
    dim3 grid(N_DIM / BN, M_DIM / BM);  // (16, 64)
    gemm_kernel<<<grid, 256, SMEM_DYN>>>(scale, bias, out);
}

// round 6
// speedup vs baseline: 1.1467x; 1.1467x over previous
#include <cuda_runtime.h>
#include <cuda_bf16.h>
#include <stdint.h>

// ---------------------------------------------------------------------------
// Problem dims (fixed)
// ---------------------------------------------------------------------------
#define M_DIM 8192
#define N_DIM 4096
#define K_DIM 4224
#define KBYTES 2112   // K/2 packed bytes per row (one int32 per byte)
#define KBLKS  264    // K/16 scale blocks per row
#define TOTA (M_DIM * KBLKS)   // 2,162,688 dequant work items for A
#define TOTB (N_DIM * KBLKS)   // 1,081,344 for B

// GEMM tiling (legacy HMMA bf16; tcgen05/fp8 unavailable or de-rated at sm_103)
#define BM 128
#define BN 128
#define BK 64
#define KITERS 66                       // 4224 / 64
#define STAGES 3
#define AB (BM * BK * 2)                // 16384 bytes per A stage
#define BB (BN * BK * 2)                // 16384 bytes per B stage
#define STB (AB + BB)                   // 32768
#define SMEM_DYN (1024 + STAGES * STB)  // 99328 bytes -> 2 CTAs/SM

// ---------------------------------------------------------------------------
// Device scratch (allocation-free rule: __device__ globals)
// ---------------------------------------------------------------------------
__device__ __nv_bfloat16 g_A[(size_t)M_DIM * K_DIM];
__device__ __nv_bfloat16 g_B[(size_t)N_DIM * K_DIM];

// ---------------------------------------------------------------------------
// Dequant (A and B in one launch): packed fp4 * 2^(sf-127) -> bf16 row-major.
// One thread per (row, 16-elem block). byte_perm LUT holds 2*|mag|.
// ---------------------------------------------------------------------------
__global__ void dequant_kernel(const int* __restrict__ packedA,
                               const int* __restrict__ sfA,
                               const int* __restrict__ packedB,
                               const int* __restrict__ sfB) {
    int idx = blockIdx.x * blockDim.x + threadIdx.x;
    const int* packed;
    const int* sf;
    __nv_bfloat16* out;
    if (idx < TOTA) {
        packed = packedA; sf = sfA; out = g_A;
    } else {
        idx -= TOTA;
        if (idx >= TOTB) return;
        packed = packedB; sf = sfB; out = g_B;
    }
    int r = idx / KBLKS;
    int b = idx - r * KBLKS;

    const int4* p = reinterpret_cast<const int4*>(packed + (size_t)r * KBYTES + b * 8);
    int4 p0 = p[0];
    int4 p1 = p[1];
    float s2 = __uint_as_float(((unsigned)sf[(size_t)r * KBLKS + b]) << 23) * 0.5f;

    int v[8] = {p0.x, p0.y, p0.z, p0.w, p1.x, p1.y, p1.z, p1.w};
    __nv_bfloat162 o[8];
#pragma unroll
    for (int i = 0; i < 8; i++) {
        int vi = v[i];
        unsigned sel = (unsigned)vi & 0x77u;
        unsigned mags = __byte_perm(0x03020100u, 0x0C080604u, sel);
        float flo = (float)(mags & 0xFFu) * s2;
        float fhi = (float)((mags >> 8) & 0xFFu) * s2;
        unsigned blo = __float_as_uint(flo) ^ (((unsigned)vi & 8u) << 28);
        unsigned bhi = __float_as_uint(fhi) ^ (((unsigned)vi & 128u) << 24);
        o[i] = __floats2bfloat162_rn(__uint_as_float(blo), __uint_as_float(bhi));
    }
    uint4* dst = reinterpret_cast<uint4*>(out + (size_t)r * K_DIM + b * 16);
    dst[0] = *reinterpret_cast<uint4*>(&o[0]);
    dst[1] = *reinterpret_cast<uint4*>(&o[4]);
}

// ---------------------------------------------------------------------------
// Helpers
// ---------------------------------------------------------------------------
__device__ __forceinline__ uint32_t smem_u32(const void* p) {
    uint32_t a;
    asm("{ .reg .u64 t; cvta.to.shared.u64 t, %1; cvt.u32.u64 %0, t; }" : "=r"(a) : "l"(p));
    return a;
}

template <int N>
__device__ __forceinline__ void cp_wait() {
    asm volatile("cp.async.wait_group %0;" :: "n"(N) : "memory");
}
__device__ __forceinline__ void cp_commit() {
    asm volatile("cp.async.commit_group;" ::: "memory");
}

__device__ __forceinline__ void ldsm4(uint32_t* r, uint32_t addr) {
    asm volatile("ldmatrix.sync.aligned.m8n8.x4.shared.b16 {%0,%1,%2,%3}, [%4];"
                 : "=r"(r[0]), "=r"(r[1]), "=r"(r[2]), "=r"(r[3]) : "r"(addr));
}

__device__ __forceinline__ void mma16816(float* d, const uint32_t* a, const uint32_t* b) {
    asm volatile(
        "mma.sync.aligned.m16n8k16.row.col.f32.bf16.bf16.f32 "
        "{%0,%1,%2,%3}, {%4,%5,%6,%7}, {%8,%9}, {%0,%1,%2,%3};"
        : "+f"(d[0]), "+f"(d[1]), "+f"(d[2]), "+f"(d[3])
        : "r"(a[0]), "r"(a[1]), "r"(a[2]), "r"(a[3]), "r"(b[0]), "r"(b[1]));
}

// Swizzle: XOR bits[6:4] with bits[9:7] (128B rows, 16B granules)
__device__ __forceinline__ uint32_t swz(uint32_t off) {
    return off ^ ((off >> 3) & 0x70);
}

// Fill one (stage, kiter): A 128x64 bf16 (16KB) + B 128x64 bf16 (16KB), SW128.
// 256 threads x 8 cp.async(16B) each.
__device__ __forceinline__ void load_stage(uint32_t tiles, int stage, int kit,
                                           int m0, int n0, int tid) {
    uint32_t sbase = tiles + stage * STB;
    int k0 = kit * BK;
#pragma unroll
    for (int i = 0; i < 4; i++) {
        int c = tid + i * 256;            // 0..1023
        int row = c >> 3, seg = c & 7;
        const __nv_bfloat16* src = g_A + (size_t)(m0 + row) * K_DIM + k0 + seg * 8;
        uint32_t dst = sbase + swz(row * 128 + seg * 16);
        asm volatile("cp.async.cg.shared.global [%0], [%1], 16;" :: "r"(dst), "l"(src));
    }
#pragma unroll
    for (int i = 0; i < 4; i++) {
        int c = tid + i * 256;
        int row = c >> 3, seg = c & 7;
        const __nv_bfloat16* src = g_B + (size_t)(n0 + row) * K_DIM + k0 + seg * 8;
        uint32_t dst = sbase + AB + swz(row * 128 + seg * 16);
        asm volatile("cp.async.cg.shared.global [%0], [%1], 16;" :: "r"(dst), "l"(src));
    }
}

// ---------------------------------------------------------------------------
// bf16 GEMM via mma.sync: CTA 128x128, 8 warps (4m x 2n), warp tile 32x64,
// 3-stage cp.async pipeline, 2 CTAs/SM (4 warps/SMSP for latency hiding).
// ---------------------------------------------------------------------------
__global__ void __launch_bounds__(256, 2)
gemm_kernel(const float* __restrict__ scale_p,
            const float* __restrict__ bias,
            float* __restrict__ out) {
    extern __shared__ char smem_raw[];
    uint32_t tiles = (smem_u32(smem_raw) + 1023) & ~1023u;

    int tid = threadIdx.x;
    int wid = tid >> 5;
    int lane = tid & 31;
    int m0 = blockIdx.y * BM;
    int n0 = blockIdx.x * BN;
    int wm = wid & 3;    // 4 m-slices of 32 rows
    int wn = wid >> 2;   // 2 n-slices of 64 cols

    float acc[2][8][4];
#pragma unroll
    for (int a = 0; a < 2; a++)
#pragma unroll
        for (int b = 0; b < 8; b++)
#pragma unroll
            for (int c = 0; c < 4; c++) acc[a][b][c] = 0.0f;

    // Prologue: fill stages 0..STAGES-2
#pragma unroll
    for (int s = 0; s < STAGES - 1; s++) {
        load_stage(tiles, s, s, m0, n0, tid);
        cp_commit();
    }

    int stage = 0;
    int lstage = STAGES - 1;
    for (int it = 0; it < KITERS; it++) {
        cp_wait<STAGES - 2>();
        __syncthreads();

        int nit = it + STAGES - 1;
        if (nit < KITERS) {
            load_stage(tiles, lstage, nit, m0, n0, tid);
            if (++lstage == STAGES) lstage = 0;
        }
        cp_commit();

        uint32_t abase = tiles + stage * STB;
        uint32_t bbase = abase + AB;
        if (++stage == STAGES) stage = 0;

#pragma unroll
        for (int ks = 0; ks < 4; ks++) {           // BK=64 -> 4 x k16
            uint32_t afr[2][4];
#pragma unroll
            for (int mf = 0; mf < 2; mf++) {
                int row = wm * 32 + mf * 16 + (lane & 15);
                uint32_t off = row * 128 + ks * 32 + ((lane >> 4) << 4);
                ldsm4(afr[mf], abase + swz(off));
            }
            uint32_t bfr[8][2];
#pragma unroll
            for (int np = 0; np < 4; np++) {       // each x4 covers two n8 groups
                int row = wn * 64 + np * 16 + (lane & 7) + ((lane >> 4) << 3);
                uint32_t off = row * 128 + ks * 32 + (((lane >> 3) & 1) << 4);
                uint32_t r[4];
                ldsm4(r, bbase + swz(off));
                bfr[np * 2 + 0][0] = r[0]; bfr[np * 2 + 0][1] = r[1];
                bfr[np * 2 + 1][0] = r[2]; bfr[np * 2 + 1][1] = r[3];
            }
#pragma unroll
            for (int mf = 0; mf < 2; mf++)
#pragma unroll
                for (int ng = 0; ng < 8; ng++)
                    mma16816(acc[mf][ng], afr[mf], bfr[ng]);
        }
    }

    // Epilogue: scale * acc + bias, f32 out (row-major [M, N])
    float sc = __ldg(scale_p);
#pragma unroll
    for (int mf = 0; mf < 2; mf++) {
#pragma unroll
        for (int ng = 0; ng < 8; ng++) {
            int m = m0 + wm * 32 + mf * 16 + (lane >> 2);
            int n = n0 + wn * 64 + ng * 8 + (lane & 3) * 2;
            float2 bb = *reinterpret_cast<const float2*>(bias + n);
            float2 v;
            v.x = acc[mf][ng][0] * sc + bb.x;
            v.y = acc[mf][ng][1] * sc + bb.y;
            *reinterpret_cast<float2*>(out + (size_t)m * N_DIM + n) = v;
            v.x = acc[mf][ng][2] * sc + bb.x;
            v.y = acc[mf][ng][3] * sc + bb.y;
            *reinterpret_cast<float2*>(out + (size_t)(m + 8) * N_DIM + n) = v;
        }
    }
}

// ---------------------------------------------------------------------------
// Launch
// ---------------------------------------------------------------------------
extern "C" void kernel_launch(void* const* d_in, const int* in_sizes, int n_in,
                              void* d_out, int out_size) {
    const int*   A_packed = (const int*)d_in[0];
    const int*   SFA      = (const int*)d_in[1];
    const float* scale    = (const float*)d_in[2];
    const int*   B_packed = (const int*)d_in[3];
    const int*   SFB      = (const int*)d_in[4];
    const float* bias     = (const float*)d_in[5];
    float*       out      = (float*)d_out;

    int tot = TOTA + TOTB;
    dequant_kernel<<<(tot + 255) / 256, 256>>>(A_packed, SFA, B_packed, SFB);

    static int configured = 0;
    if (!configured) {
        cudaFuncSetAttribute(gemm_kernel, cudaFuncAttributeMaxDynamicSharedMemorySize, SMEM_DYN);
        configured = 1;
    }
    dim3 grid(N_DIM / BN, M_DIM / BM);  // (32, 64)
    gemm_kernel<<<grid, 256, SMEM_DYN>>>(scale, bias, out);
}